// round 4
// baseline (speedup 1.0000x reference)
#include <cuda_runtime.h>
#include <cstdint>

// ---------------------------------------------------------------------------
// RPN target assignment: anchors [A,4] vs gt_boxes [G,4]
// Outputs (concatenated float32): rpn_match [A], rpn_bbox [A,4], num_pos [1]
// ---------------------------------------------------------------------------

#define MAX_A 262144
#define MAX_G 256
#define TPB   256

__device__ int g_mask_kind;   // 0 = uint8/bool, 1 = int32, 2 = float32
__device__ int g_any_crowd;
__device__ int g_num_pos;
__device__ unsigned long long g_colkey[MAX_G];
__device__ int g_flags[MAX_A];   // bit0: iou>=0.7, bit1: iou<0.3, bit2: no_crowd, bit3: pos_from_gt
__device__ int g_bestg[MAX_A];

__device__ __forceinline__ bool mask_at(const void* m, int kind, int i) {
    if (kind == 0) return ((const unsigned char*)m)[i] != 0;
    if (kind == 1) return ((const int*)m)[i] != 0;
    return ((const float*)m)[i] != 0.0f;
}

// monotone float->uint transform (preserves ordering incl. negatives)
__device__ __forceinline__ unsigned mono_f2u(float f) {
    unsigned u = __float_as_uint(f);
    return (u & 0x80000000u) ? ~u : (u | 0x80000000u);
}

// --------------------------- setup / detection ------------------------------
__global__ void k_setup(const void* mask, int A, const int* gt_cls, int G) {
    int t = threadIdx.x;
    __shared__ int s_any;
    if (t == 0) {
        s_any = 0;
        // detect mask storage dtype from byte pattern (values are 0/1 booleans)
        const unsigned char* p = (const unsigned char*)mask;
        int nbytes = A < 1024 ? A : 1024;
        int nz0 = 0, nz1 = 0, nz2 = 0, nz3 = 0;
        for (int i = 0; i + 3 < nbytes; i += 4) {
            nz0 += (p[i + 0] != 0);
            nz1 += (p[i + 1] != 0);
            nz2 += (p[i + 2] != 0);
            nz3 += (p[i + 3] != 0);
        }
        int kind;
        if (nz0 == 0 && (nz2 + nz3) > 0)           kind = 2;  // float32 (1.0f = 00 00 80 3F)
        else if (nz1 == 0 && nz2 == 0 && nz3 == 0) kind = 1;  // int32 LE 0/1
        else                                        kind = 0;  // bool / uint8
        g_mask_kind = kind;
        g_num_pos = 0;
    }
    __syncthreads();
    for (int g = t; g < G; g += TPB)
        if (gt_cls[g] < 0) atomicOr(&s_any, 1);
    __syncthreads();
    if (t == 0) g_any_crowd = s_any;
    // init column keys to (iou = -1.0, idx = 0)  -> matches argmax of all-(-1) rows
    for (int g = t; g < MAX_G; g += TPB)
        g_colkey[g] = ((unsigned long long)mono_f2u(-1.0f) << 32) | 0xFFFFFFFFull;
}

// ------------------------------ main pass -----------------------------------
__global__ void __launch_bounds__(TPB) k_main(
    const float4* __restrict__ anchors, const void* __restrict__ mask,
    const int* __restrict__ gt_cls, const float4* __restrict__ gtb,
    int A, int G)
{
    __shared__ float4 s_gbox[MAX_G];
    __shared__ float  s_garea[MAX_G];
    __shared__ unsigned char s_gcrowd[MAX_G];
    __shared__ float4 s_abox[TPB];
    __shared__ float  s_aarea[TPB];   // < 0 => invalid / out-of-range (skip in col pass)

    const int t = threadIdx.x;
    const int kind = g_mask_kind;
    const int anyc = g_any_crowd;

    for (int g = t; g < G; g += TPB) {
        float4 b = gtb[g];
        s_gbox[g]   = b;
        s_garea[g]  = (b.z - b.x) * (b.w - b.y);
        s_gcrowd[g] = (gt_cls[g] < 0);
    }

    const int a = blockIdx.x * TPB + t;
    float4 ab = make_float4(0.f, 0.f, 0.f, 0.f);
    float aarea = 0.f;
    bool inrange = (a < A), valid = false;
    if (inrange) {
        ab    = anchors[a];
        aarea = (ab.z - ab.x) * (ab.w - ab.y);
        valid = mask_at(mask, kind, a);
    }
    s_abox[t]  = ab;
    s_aarea[t] = (inrange && valid) ? aarea : -1.0f;
    __syncthreads();

    // ---------------- phase 1: row max/argmax over GTs (crowd-masked) --------
    if (inrange) {
        float bi = -1.0f, bc = 1.0f;   // best (inter, area_a+area_g); iou = bi/(bc-bi)
        int   bg = 0;
        float ci = -1.0f, cc = 1.0f;   // crowd best

        if (!anyc) {
            #pragma unroll 4
            for (int g = 0; g < G; g++) {
                float4 gb = s_gbox[g];
                float iy1 = fmaxf(ab.x, gb.x);
                float ix1 = fmaxf(ab.y, gb.y);
                float iy2 = fminf(ab.z, gb.z);
                float ix2 = fminf(ab.w, gb.w);
                float ih = fmaxf(iy2 - iy1, 0.0f);
                float iw = fmaxf(ix2 - ix1, 0.0f);
                float inter = ih * iw;
                float c = aarea + s_garea[g];
                if (inter * bc > bi * c) { bi = inter; bc = c; bg = g; }
            }
        } else {
            for (int g = 0; g < G; g++) {
                float4 gb = s_gbox[g];
                float iy1 = fmaxf(ab.x, gb.x);
                float ix1 = fmaxf(ab.y, gb.y);
                float iy2 = fminf(ab.z, gb.z);
                float ix2 = fminf(ab.w, gb.w);
                float ih = fmaxf(iy2 - iy1, 0.0f);
                float iw = fmaxf(ix2 - ix1, 0.0f);
                float inter = ih * iw;
                float c = aarea + s_garea[g];
                if (s_gcrowd[g]) {
                    if (inter * cc > ci * c) { ci = inter; cc = c; }
                } else {
                    if (inter * bc > bi * c) { bi = inter; bc = c; bg = g; }
                }
            }
        }

        float bu = bc - bi;  // union of the best pair
        int fl = 0;
        if (bi >= 0.7f * bu) fl |= 1;
        if (bi <  0.3f * bu) fl |= 2;
        bool no_crowd = true;
        if (anyc) no_crowd = (ci < 0.001f * (cc - ci));
        if (no_crowd) fl |= 4;
        g_flags[a] = fl;
        g_bestg[a] = bg;
    }

    // ---------------- phase 2: column argmax over this anchor tile -----------
    if (t < G) {
        float4 gb = s_gbox[t];
        float garea = s_garea[t];
        float bi = -1.0f, bc = 1.0f;
        int   ba = -1;
        #pragma unroll 4
        for (int j = 0; j < TPB; j++) {
            float sa = s_aarea[j];             // broadcast read, uniform branch
            if (sa < 0.0f) continue;
            float4 xb = s_abox[j];
            float iy1 = fmaxf(xb.x, gb.x);
            float ix1 = fmaxf(xb.y, gb.y);
            float iy2 = fminf(xb.z, gb.z);
            float ix2 = fminf(xb.w, gb.w);
            float ih = fmaxf(iy2 - iy1, 0.0f);
            float iw = fmaxf(ix2 - ix1, 0.0f);
            float inter = ih * iw;
            float c = sa + garea;
            if (inter * bc > bi * c) { bi = inter; bc = c; ba = j; }
        }
        if (ba >= 0) {
            float iou = bi / (bc - bi);        // one div per column per block
            unsigned idx = (unsigned)(blockIdx.x * TPB + ba);
            unsigned long long key =
                ((unsigned long long)mono_f2u(iou) << 32) | (unsigned long long)(~idx);
            atomicMax(&g_colkey[t], key);      // max iou, tie -> smaller anchor idx
        }
    }
}

// --------------------- scatter pos_from_gt (non-crowd GTs) ------------------
__global__ void k_scatter(const int* __restrict__ gt_cls, int G, int A) {
    int g = blockIdx.x * blockDim.x + threadIdx.x;
    if (g < G && gt_cls[g] >= 0) {
        unsigned idx = ~(unsigned)(g_colkey[g] & 0xFFFFFFFFull);
        if (idx < (unsigned)A) atomicOr(&g_flags[idx], 8);
    }
}

// ------------------------------- finalize -----------------------------------
__global__ void __launch_bounds__(TPB) k_final(
    const float4* __restrict__ anchors, const void* __restrict__ mask,
    const float4* __restrict__ gtb, const float* __restrict__ stddev,
    float* __restrict__ out, int A)
{
    int a = blockIdx.x * TPB + threadIdx.x;
    bool pos_valid = false;
    if (a < A) {
        int fl = g_flags[a];
        bool valid = mask_at(mask, g_mask_kind, a);
        bool positive = (fl & 9) != 0;                        // iou>=0.7 | pos_from_gt
        bool negative = ((fl & 2) != 0) && ((fl & 4) != 0) && !positive;
        int match = positive ? 1 : (negative ? -1 : 0);
        if (!valid) match = 0;
        out[a] = (float)match;

        pos_valid = positive && valid;
        float4 d = make_float4(0.f, 0.f, 0.f, 0.f);
        if (pos_valid) {
            float4 m  = gtb[g_bestg[a]];
            float4 ab = anchors[a];
            // faithful to source bug: size = b[2:4] + b[0:2]; centre = size*0.5
            float gsy = m.z + m.x,  gsx = m.w + m.y;
            float asy = ab.z + ab.x, asx = ab.w + ab.y;
            float gcy = gsy * 0.5f, gcx = gsx * 0.5f;
            float acy = asy * 0.5f, acx = asx * 0.5f;
            d.x = ((gcy - acy) / asy) / stddev[0];
            d.y = ((gcx - acx) / asx) / stddev[1];
            d.z = logf(gsy / asy) / stddev[2];
            d.w = logf(gsx / asx) / stddev[3];
        }
        reinterpret_cast<float4*>(out + A)[a] = d;
    }
    unsigned bal = __ballot_sync(0xFFFFFFFFu, pos_valid);
    if ((threadIdx.x & 31) == 0 && bal) atomicAdd(&g_num_pos, __popc(bal));
}

__global__ void k_count(float* out, int A) {
    if (threadIdx.x == 0) out[5 * A] = (float)g_num_pos;
}

// ------------------------------- launcher -----------------------------------
extern "C" void kernel_launch(void* const* d_in, const int* in_sizes, int n_in,
                              void* d_out, int out_size) {
    const float4* anchors = (const float4*)d_in[0];
    const void*   mask    = d_in[1];
    const int*    gt_cls  = (const int*)d_in[2];
    const float4* gtb     = (const float4*)d_in[3];
    const float*  stddev  = (const float*)d_in[4];
    int A = in_sizes[0] / 4;
    int G = in_sizes[2];
    float* out = (float*)d_out;
    int nb = (A + TPB - 1) / TPB;

    k_setup  <<<1,  TPB>>>(mask, A, gt_cls, G);
    k_main   <<<nb, TPB>>>(anchors, mask, gt_cls, gtb, A, G);
    k_scatter<<<1,  TPB>>>(gt_cls, G, A);
    k_final  <<<nb, TPB>>>(anchors, mask, gtb, stddev, out, A);
    k_count  <<<1,  32>>>(out, A);
}

// round 6
// speedup vs baseline: 1.0380x; 1.0380x over previous
#include <cuda_runtime.h>
#include <cstdint>

// ---------------------------------------------------------------------------
// RPN target assignment with spatial binning.
// Outputs (float32): rpn_match [A], rpn_bbox [A,4], num_pos [1]
// ---------------------------------------------------------------------------

#define MAX_A 262144
#define MAXG  512
#define TPB   256
#define NB    32
#define NBB   (NB*NB)   // 1024 bins

__device__ int g_mask_kind;        // 0=uint8, 1=int32, 2=float32
__device__ int g_any_crowd;
__device__ int g_num_pos;
__device__ int g_ticket;           // zero-init; self-resetting
__device__ int g_first_valid;     // min anchor idx with valid mask (else INT_MAX)
__device__ int g_first_noncrowd;  // min g with cls>=0 (else 0)
__device__ unsigned g_maxgh_b, g_maxgw_b;   // max GT h/w (float bits, >=0)
__device__ unsigned g_maxah_b, g_maxaw_b;   // max anchor h/w
__device__ int g_ahist[NBB];
__device__ int g_abinstart[NBB + 1];
__device__ int g_acur[NBB];
__device__ int g_gstart[NBB + 1];
__device__ float4 g_gbox[MAXG];
__device__ float  g_garea[MAXG];
__device__ int    g_gmeta[MAXG];          // orig g | (crowd ? 0x80000000 : 0)
__device__ float4 g_sbox[MAX_A];          // anchors sorted by bin
__device__ float  g_saav[MAX_A];          // +area if valid, -area if invalid
__device__ int    g_sidx[MAX_A];          // orig anchor index
__device__ unsigned long long g_colkey[MAXG];
__device__ int g_flags[MAX_A];  // bit0:iou>=.7 bit1:iou<.3 bit2:no_crowd bit3:pos_from_gt
__device__ int g_bestg[MAX_A];

__device__ __forceinline__ bool mask_at(const void* m, int kind, int i) {
    if (kind == 0) return ((const unsigned char*)m)[i] != 0;
    if (kind == 1) return ((const int*)m)[i] != 0;
    return ((const float*)m)[i] != 0.0f;
}

__device__ __forceinline__ unsigned mono_f2u(float f) {
    unsigned u = __float_as_uint(f);
    return (u & 0x80000000u) ? ~u : (u | 0x80000000u);
}

__device__ __forceinline__ int binOf(float v) {
    int b = (int)(v * 0.03125f);            // /32, v >= 0 at call sites
    return b < 0 ? 0 : (b > NB - 1 ? NB - 1 : b);
}

// ------------------- prep: GT binning + misc detection ----------------------
__global__ void __launch_bounds__(TPB) k_prep(const void* mask, int A,
        const int* __restrict__ gt_cls, const float4* __restrict__ gtb, int G) {
    __shared__ int sh[NBB];
    __shared__ int ssum[TPB];
    __shared__ int s_any, s_fnc;
    __shared__ unsigned s_mh, s_mw;
    int t = threadIdx.x;
    if (t == 0) { s_any = 0; s_fnc = 0x7FFFFFFF; s_mh = 0; s_mw = 0; }
    for (int i = t; i < NBB; i += TPB) { sh[i] = 0; g_ahist[i] = 0; }
    __syncthreads();

    float4 b = make_float4(0.f, 0.f, 0.f, 0.f);
    int mybin = -1; bool crowd = false;
    if (t < G) {
        b = gtb[t];
        crowd = gt_cls[t] < 0;
        mybin = binOf(b.x) * NB + binOf(b.y);
        atomicAdd(&sh[mybin], 1);
        atomicMax(&s_mh, __float_as_uint(b.z - b.x));
        atomicMax(&s_mw, __float_as_uint(b.w - b.y));
        if (crowd) atomicOr(&s_any, 1); else atomicMin(&s_fnc, t);
    }
    if (t == 0) {
        // mask dtype detection from byte pattern (values are 0/1 booleans)
        const unsigned char* p = (const unsigned char*)mask;
        int nbytes = A < 1024 ? A : 1024;
        int nz0 = 0, nz1 = 0, nz2 = 0, nz3 = 0;
        for (int i = 0; i + 3 < nbytes; i += 4) {
            nz0 += (p[i] != 0); nz1 += (p[i + 1] != 0);
            nz2 += (p[i + 2] != 0); nz3 += (p[i + 3] != 0);
        }
        int kind;
        if (nz0 == 0 && (nz2 + nz3) > 0)            kind = 2;
        else if (nz1 == 0 && nz2 == 0 && nz3 == 0)  kind = 1;
        else                                        kind = 0;
        g_mask_kind = kind;
        g_num_pos = 0;
        g_first_valid = 0x7FFFFFFF;
        g_maxah_b = 0; g_maxaw_b = 0;
    }
    __syncthreads();
    if (t == 0) {
        g_any_crowd = s_any;
        g_first_noncrowd = (s_fnc == 0x7FFFFFFF) ? 0 : s_fnc;
        g_maxgh_b = s_mh; g_maxgw_b = s_mw;
    }
    // exclusive scan of sh[NBB] in place (4 bins per thread)
    int base = t * 4;
    int c0 = sh[base], c1 = sh[base + 1], c2 = sh[base + 2], c3 = sh[base + 3];
    int local = c0 + c1 + c2 + c3;
    ssum[t] = local;
    __syncthreads();
    for (int off = 1; off < TPB; off <<= 1) {
        int v = (t >= off) ? ssum[t - off] : 0;
        __syncthreads();
        ssum[t] += v;
        __syncthreads();
    }
    int excl = ssum[t] - local;
    sh[base]     = excl;
    sh[base + 1] = excl + c0;
    sh[base + 2] = excl + c0 + c1;
    sh[base + 3] = excl + c0 + c1 + c2;
    g_gstart[base] = sh[base];
    g_gstart[base + 1] = sh[base + 1];
    g_gstart[base + 2] = sh[base + 2];
    g_gstart[base + 3] = sh[base + 3];
    if (t == 0) g_gstart[NBB] = G;
    __syncthreads();
    // scatter GTs into bin-sorted arrays
    if (t < G) {
        int pos = atomicAdd(&sh[mybin], 1);
        g_gbox[pos]  = b;
        g_garea[pos] = (b.z - b.x) * (b.w - b.y);
        g_gmeta[pos] = t | (crowd ? 0x80000000 : 0);
    }
}

// -------------------- anchor histogram + maxes + first_valid ----------------
__global__ void __launch_bounds__(TPB) k_hist(const float4* __restrict__ anchors,
                                              const void* __restrict__ mask, int A) {
    __shared__ int sh[NBB];
    __shared__ unsigned s_mh, s_mw; __shared__ int s_fv;
    int t = threadIdx.x;
    if (t == 0) { s_mh = 0; s_mw = 0; s_fv = 0x7FFFFFFF; }
    for (int i = t; i < NBB; i += TPB) sh[i] = 0;
    __syncthreads();
    int a = blockIdx.x * TPB + t;
    unsigned hb = 0, wb = 0; int fv = 0x7FFFFFFF;
    if (a < A) {
        float4 b = anchors[a];
        atomicAdd(&sh[binOf(b.x) * NB + binOf(b.y)], 1);
        hb = __float_as_uint(b.z - b.x);
        wb = __float_as_uint(b.w - b.y);
        if (mask_at(mask, g_mask_kind, a)) fv = a;
    }
    unsigned mh = __reduce_max_sync(0xFFFFFFFFu, hb);
    unsigned mw = __reduce_max_sync(0xFFFFFFFFu, wb);
    int mf = __reduce_min_sync(0xFFFFFFFFu, fv);
    if ((t & 31) == 0) {
        atomicMax(&s_mh, mh); atomicMax(&s_mw, mw); atomicMin(&s_fv, mf);
    }
    __syncthreads();
    for (int i = t; i < NBB; i += TPB) { int c = sh[i]; if (c) atomicAdd(&g_ahist[i], c); }
    if (t == 0) {
        atomicMax(&g_maxah_b, s_mh);
        atomicMax(&g_maxaw_b, s_mw);
        if (s_fv != 0x7FFFFFFF) atomicMin(&g_first_valid, s_fv);
    }
}

// -------------------- scan anchor hist + init column keys -------------------
__global__ void __launch_bounds__(NBB) k_scan(int A) {
    __shared__ int s[NBB];
    int t = threadIdx.x;
    int c = g_ahist[t];
    s[t] = c;
    __syncthreads();
    for (int off = 1; off < NBB; off <<= 1) {
        int v = (t >= off) ? s[t - off] : 0;
        __syncthreads();
        s[t] += v;
        __syncthreads();
    }
    int excl = s[t] - c;
    g_abinstart[t] = excl;
    g_acur[t] = excl;
    if (t == NBB - 1) g_abinstart[NBB] = s[t];
    if (t < MAXG) {
        int fv = g_first_valid;
        unsigned long long key;
        if (fv < A)  // (iou=0, idx=first_valid): argmax when column has no positive iou
            key = ((unsigned long long)0x80000000u << 32) | (unsigned long long)(~(unsigned)fv);
        else         // all invalid: argmax of all-(-1) = 0
            key = ((unsigned long long)0x407FFFFFu << 32) | 0xFFFFFFFFull;
        g_colkey[t] = key;
    }
}

// ------------------------- scatter anchors into bins ------------------------
__global__ void __launch_bounds__(TPB) k_scat(const float4* __restrict__ anchors,
                                              const void* __restrict__ mask, int A) {
    int a = blockIdx.x * TPB + threadIdx.x;
    if (a >= A) return;
    float4 b = anchors[a];
    int bin = binOf(b.x) * NB + binOf(b.y);
    int p = atomicAdd(&g_acur[bin], 1);
    float area = (b.z - b.x) * (b.w - b.y);
    bool valid = mask_at(mask, g_mask_kind, a);
    g_sbox[p] = b;
    g_saav[p] = valid ? area : -area;
    g_sidx[p] = a;
}

// ---------------- row pass: per-anchor max/argmax over windowed GTs ---------
__global__ void __launch_bounds__(TPB) k_row(int A, int G) {
    __shared__ float4 s_gb[MAXG];
    __shared__ float  s_ga[MAXG];
    __shared__ int    s_gm[MAXG];
    __shared__ int    s_gs[NBB + 1];
    int t = threadIdx.x;
    for (int i = t; i < G; i += TPB) {
        s_gb[i] = g_gbox[i]; s_ga[i] = g_garea[i]; s_gm[i] = g_gmeta[i];
    }
    for (int i = t; i < NBB + 1; i += TPB) s_gs[i] = g_gstart[i];
    __syncthreads();

    int p = blockIdx.x * TPB + t;
    if (p >= A) return;
    float4 ab = g_sbox[p];
    float aarea = fabsf(g_saav[p]);
    int orig = g_sidx[p];

    float maxgh = __uint_as_float(g_maxgh_b), maxgw = __uint_as_float(g_maxgw_b);
    float maxah = __uint_as_float(g_maxah_b), maxaw = __uint_as_float(g_maxaw_b);
    int aby = binOf(ab.x), abx = binOf(ab.y);
    // uniform-per-bin superset window: g.y1 in (aby*32 - maxgh, aby*32+32 + maxah)
    int by0 = binOf(fmaxf(aby * 32.f - maxgh, 0.f));
    int by1 = binOf(aby * 32.f + 32.f + maxah);
    int bx0 = binOf(fmaxf(abx * 32.f - maxgw, 0.f));
    int bx1 = binOf(abx * 32.f + 32.f + maxaw);

    float bi = 0.f, bc = 1.f;           // best (inter, area_a+area_g); iou = bi/(bc-bi)
    int bg = g_first_noncrowd;          // argmax default = first non-crowd GT
    float ci = 0.f, cc = 1.f;           // crowd best

    for (int by = by0; by <= by1; by++) {
        int s = s_gs[by * NB + bx0];
        int e = s_gs[by * NB + bx1 + 1];
        for (int i = s; i < e; i++) {
            float4 gb = s_gb[i];
            float iy1 = fmaxf(ab.x, gb.x);
            float ix1 = fmaxf(ab.y, gb.y);
            float iy2 = fminf(ab.z, gb.z);
            float ix2 = fminf(ab.w, gb.w);
            float inter = fmaxf(iy2 - iy1, 0.f) * fmaxf(ix2 - ix1, 0.f);
            float c = aarea + s_ga[i];
            int m = s_gm[i];
            if (m < 0) { if (inter * cc > ci * c) { ci = inter; cc = c; } }
            else       { if (inter * bc > bi * c) { bi = inter; bc = c; bg = m; } }
        }
    }
    float bu = bc - bi;
    int fl = 0;
    if (bi >= 0.7f * bu) fl |= 1;
    if (bi <  0.3f * bu) fl |= 2;
    if (ci < 0.001f * (cc - ci)) fl |= 4;     // no_crowd (trivially true if no crowd hits)
    g_flags[orig] = fl;
    g_bestg[orig] = bg;
}

// -------------- column pass: per-GT argmax over windowed valid anchors ------
__global__ void __launch_bounds__(TPB) k_col(const float4* __restrict__ gtb, int A) {
    __shared__ float s_bi[TPB], s_bc[TPB];
    __shared__ int s_bp[TPB];
    int g = blockIdx.x;
    int t = threadIdx.x;
    float4 gb = gtb[g];
    float garea = (gb.z - gb.x) * (gb.w - gb.y);
    float maxah = __uint_as_float(g_maxah_b), maxaw = __uint_as_float(g_maxaw_b);
    int by0 = binOf(fmaxf(gb.x - maxah, 0.f));
    int by1 = binOf(gb.z);
    int bx0 = binOf(fmaxf(gb.y - maxaw, 0.f));
    int bx1 = binOf(gb.w);

    float bi = 0.f, bc = 1.f; int bp = -1;
    for (int by = by0; by <= by1; by++) {
        int s = g_abinstart[by * NB + bx0];
        int e = g_abinstart[by * NB + bx1 + 1];
        for (int i = s + t; i < e; i += TPB) {
            float av = g_saav[i];
            if (av <= 0.f) continue;         // invalid anchor
            float4 ab = g_sbox[i];
            float iy1 = fmaxf(ab.x, gb.x);
            float ix1 = fmaxf(ab.y, gb.y);
            float iy2 = fminf(ab.z, gb.z);
            float ix2 = fminf(ab.w, gb.w);
            float inter = fmaxf(iy2 - iy1, 0.f) * fmaxf(ix2 - ix1, 0.f);
            float c = av + garea;
            if (inter * bc > bi * c) { bi = inter; bc = c; bp = i; }
        }
    }
    s_bi[t] = bi; s_bc[t] = bc; s_bp[t] = bp;
    __syncthreads();
    for (int off = TPB / 2; off > 0; off >>= 1) {
        if (t < off) {
            float oi = s_bi[t + off], oc = s_bc[t + off];
            if (oi * s_bc[t] > s_bi[t] * oc) {
                s_bi[t] = oi; s_bc[t] = oc; s_bp[t] = s_bp[t + off];
            }
        }
        __syncthreads();
    }
    if (t == 0 && s_bp[0] >= 0) {
        int idx = g_sidx[s_bp[0]];
        float iou = s_bi[0] / (s_bc[0] - s_bi[0]);
        unsigned long long key =
            ((unsigned long long)mono_f2u(iou) << 32) | (unsigned long long)(~(unsigned)idx);
        atomicMax(&g_colkey[g], key);
    }
}

// --------------------- scatter pos_from_gt (non-crowd GTs) ------------------
__global__ void k_posgt(const int* __restrict__ gt_cls, int G, int A) {
    int g = blockIdx.x * blockDim.x + threadIdx.x;
    if (g < G && gt_cls[g] >= 0) {
        unsigned idx = ~(unsigned)(g_colkey[g] & 0xFFFFFFFFull);
        if (idx < (unsigned)A) atomicOr(&g_flags[idx], 8);
    }
}

// ------------------------------- finalize -----------------------------------
__global__ void __launch_bounds__(TPB) k_final(
    const float4* __restrict__ anchors, const void* __restrict__ mask,
    const float4* __restrict__ gtb, const float* __restrict__ stddev,
    float* __restrict__ out, int A)
{
    int a = blockIdx.x * TPB + threadIdx.x;
    bool pos_valid = false;
    if (a < A) {
        int fl = g_flags[a];
        bool valid = mask_at(mask, g_mask_kind, a);
        bool positive = (fl & 9) != 0;
        bool negative = ((fl & 2) != 0) && ((fl & 4) != 0) && !positive;
        int match = positive ? 1 : (negative ? -1 : 0);
        if (!valid) match = 0;
        out[a] = (float)match;

        pos_valid = positive && valid;
        float4 d = make_float4(0.f, 0.f, 0.f, 0.f);
        if (pos_valid) {
            float4 m  = gtb[g_bestg[a]];
            float4 ab = anchors[a];
            // faithful to source bug: size = b[2:4] + b[0:2]
            float gsy = m.z + m.x,   gsx = m.w + m.y;
            float asy = ab.z + ab.x, asx = ab.w + ab.y;
            float gcy = gsy * 0.5f, gcx = gsx * 0.5f;
            float acy = asy * 0.5f, acx = asx * 0.5f;
            d.x = ((gcy - acy) / asy) / stddev[0];
            d.y = ((gcx - acx) / asx) / stddev[1];
            d.z = logf(gsy / asy) / stddev[2];
            d.w = logf(gsx / asx) / stddev[3];
        }
        reinterpret_cast<float4*>(out + A)[a] = d;
    }
    unsigned bal = __ballot_sync(0xFFFFFFFFu, pos_valid);
    if ((threadIdx.x & 31) == 0 && bal) atomicAdd(&g_num_pos, __popc(bal));
    __syncthreads();
    if (threadIdx.x == 0) {
        __threadfence();
        int tk = atomicAdd(&g_ticket, 1);
        if (tk == (int)gridDim.x - 1) {
            g_ticket = 0;
            out[5 * A] = (float)atomicAdd(&g_num_pos, 0);
        }
    }
}

// ------------------------------- launcher -----------------------------------
extern "C" void kernel_launch(void* const* d_in, const int* in_sizes, int n_in,
                              void* d_out, int out_size) {
    const float4* anchors = (const float4*)d_in[0];
    const void*   mask    = d_in[1];
    const int*    gt_cls  = (const int*)d_in[2];
    const float4* gtb     = (const float4*)d_in[3];
    const float*  stddev  = (const float*)d_in[4];
    int A = in_sizes[0] / 4;
    int G = in_sizes[2];
    float* out = (float*)d_out;
    int nb = (A + TPB - 1) / TPB;

    k_prep <<<1,  TPB>>>(mask, A, gt_cls, gtb, G);
    k_hist <<<nb, TPB>>>(anchors, mask, A);
    k_scan <<<1,  NBB>>>(A);
    k_scat <<<nb, TPB>>>(anchors, mask, A);
    k_row  <<<nb, TPB>>>(A, G);
    k_col  <<<G,  TPB>>>(gtb, A);
    k_posgt<<<(G + TPB - 1) / TPB, TPB>>>(gt_cls, G, A);
    k_final<<<nb, TPB>>>(anchors, mask, gtb, stddev, out, A);
}

// round 7
// speedup vs baseline: 1.4517x; 1.3986x over previous
#include <cuda_runtime.h>
#include <cstdint>

// ---------------------------------------------------------------------------
// RPN target assignment with spatial binning + atomic-free counting sort.
// Outputs (float32): rpn_match [A], rpn_bbox [A,4], num_pos [1]
// ---------------------------------------------------------------------------

#define MAX_A 262144
#define MAXG  512
#define TPB   256
#define NB    32
#define NBB   (NB*NB)     // 1024 bins
#define NBLK  1024        // max anchor blocks (MAX_A / TPB)

__device__ int g_mask_kind;        // 0=uint8, 1=int32, 2=float32
__device__ int g_num_pos;
__device__ int g_ticket;           // zero-init; self-resetting
__device__ int g_first_valid;      // min anchor idx with valid mask (else INT_MAX)
__device__ int g_first_noncrowd;   // min g with cls>=0 (else 0)
__device__ unsigned g_maxgh_b, g_maxgw_b;   // max GT h/w (float bits, >=0)
__device__ unsigned g_maxah_b, g_maxaw_b;   // max anchor h/w
__device__ int g_bh[NBLK * NBB];   // per-block bin counts -> exclusive offsets
__device__ int g_ahist[NBB];       // bin totals
__device__ int g_abinstart[NBB + 1];
__device__ int g_gstart[NBB + 1];
__device__ float4 g_gbox[MAXG];
__device__ float  g_garea[MAXG];
__device__ int    g_gmeta[MAXG];   // orig g | (crowd ? 0x80000000 : 0)
__device__ float4 g_spack[2 * MAX_A]; // [2p]=box, [2p+1]=(signed_area, idx_bits, 0, 0)
__device__ unsigned long long g_colkey[MAXG];
__device__ int g_fb[MAX_A];        // bits0-3: flags, bits4+: best GT index

__device__ __forceinline__ bool mask_at(const void* m, int kind, int i) {
    if (kind == 0) return ((const unsigned char*)m)[i] != 0;
    if (kind == 1) return ((const int*)m)[i] != 0;
    return ((const float*)m)[i] != 0.0f;
}

__device__ __forceinline__ unsigned mono_f2u(float f) {
    unsigned u = __float_as_uint(f);
    return (u & 0x80000000u) ? ~u : (u | 0x80000000u);
}

__device__ __forceinline__ int binOf(float v) {
    int b = (int)(v * 0.03125f);            // /32, v >= 0 at call sites
    return b < 0 ? 0 : (b > NB - 1 ? NB - 1 : b);
}

// ------------------- prep: GT binning + misc detection ----------------------
__global__ void __launch_bounds__(TPB) k_prep(const void* mask, int A,
        const int* __restrict__ gt_cls, const float4* __restrict__ gtb, int G) {
    __shared__ int sh[NBB];
    __shared__ int ssum[TPB];
    __shared__ int s_fnc;
    __shared__ unsigned s_mh, s_mw;
    int t = threadIdx.x;
    if (t == 0) { s_fnc = 0x7FFFFFFF; s_mh = 0; s_mw = 0; }
    for (int i = t; i < NBB; i += TPB) sh[i] = 0;
    __syncthreads();

    float4 b = make_float4(0.f, 0.f, 0.f, 0.f);
    int mybin = -1; bool crowd = false;
    if (t < G) {
        b = gtb[t];
        crowd = gt_cls[t] < 0;
        mybin = binOf(b.x) * NB + binOf(b.y);
        atomicAdd(&sh[mybin], 1);
        atomicMax(&s_mh, __float_as_uint(b.z - b.x));
        atomicMax(&s_mw, __float_as_uint(b.w - b.y));
        if (!crowd) atomicMin(&s_fnc, t);
    }
    if (t == 0) {
        // mask dtype detection from byte pattern (values are 0/1 booleans)
        const unsigned char* p = (const unsigned char*)mask;
        int nbytes = A < 1024 ? A : 1024;
        int nz0 = 0, nz1 = 0, nz2 = 0, nz3 = 0;
        for (int i = 0; i + 3 < nbytes; i += 4) {
            nz0 += (p[i] != 0); nz1 += (p[i + 1] != 0);
            nz2 += (p[i + 2] != 0); nz3 += (p[i + 3] != 0);
        }
        int kind;
        if (nz0 == 0 && (nz2 + nz3) > 0)            kind = 2;
        else if (nz1 == 0 && nz2 == 0 && nz3 == 0)  kind = 1;
        else                                        kind = 0;
        g_mask_kind = kind;
        g_num_pos = 0;
        g_first_valid = 0x7FFFFFFF;
        g_maxah_b = 0; g_maxaw_b = 0;
    }
    __syncthreads();
    if (t == 0) {
        g_first_noncrowd = (s_fnc == 0x7FFFFFFF) ? 0 : s_fnc;
        g_maxgh_b = s_mh; g_maxgw_b = s_mw;
    }
    // exclusive scan of sh[NBB] in place (4 bins per thread)
    int base = t * 4;
    int c0 = sh[base], c1 = sh[base + 1], c2 = sh[base + 2], c3 = sh[base + 3];
    int local = c0 + c1 + c2 + c3;
    ssum[t] = local;
    __syncthreads();
    for (int off = 1; off < TPB; off <<= 1) {
        int v = (t >= off) ? ssum[t - off] : 0;
        __syncthreads();
        ssum[t] += v;
        __syncthreads();
    }
    int excl = ssum[t] - local;
    sh[base]     = excl;
    sh[base + 1] = excl + c0;
    sh[base + 2] = excl + c0 + c1;
    sh[base + 3] = excl + c0 + c1 + c2;
    g_gstart[base]     = sh[base];
    g_gstart[base + 1] = sh[base + 1];
    g_gstart[base + 2] = sh[base + 2];
    g_gstart[base + 3] = sh[base + 3];
    if (t == 0) g_gstart[NBB] = G;
    __syncthreads();
    // scatter GTs into bin-sorted arrays
    if (t < G) {
        int pos = atomicAdd(&sh[mybin], 1);
        g_gbox[pos]  = b;
        g_garea[pos] = (b.z - b.x) * (b.w - b.y);
        g_gmeta[pos] = t | (crowd ? 0x80000000 : 0);
    }
}

// ------------- anchor per-block histogram (no global atomics) ---------------
__global__ void __launch_bounds__(TPB) k_hist(const float4* __restrict__ anchors,
                                              const void* __restrict__ mask, int A) {
    __shared__ int sh[NBB];
    __shared__ unsigned s_mh, s_mw; __shared__ int s_fv;
    int t = threadIdx.x;
    if (t == 0) { s_mh = 0; s_mw = 0; s_fv = 0x7FFFFFFF; }
    for (int i = t; i < NBB; i += TPB) sh[i] = 0;
    __syncthreads();
    int a = blockIdx.x * TPB + t;
    unsigned hb = 0, wb = 0; int fv = 0x7FFFFFFF;
    if (a < A) {
        float4 b = anchors[a];
        atomicAdd(&sh[binOf(b.x) * NB + binOf(b.y)], 1);
        hb = __float_as_uint(b.z - b.x);
        wb = __float_as_uint(b.w - b.y);
        if (mask_at(mask, g_mask_kind, a)) fv = a;
    }
    unsigned mh = __reduce_max_sync(0xFFFFFFFFu, hb);
    unsigned mw = __reduce_max_sync(0xFFFFFFFFu, wb);
    int mf = __reduce_min_sync(0xFFFFFFFFu, fv);
    if ((t & 31) == 0) {
        atomicMax(&s_mh, mh); atomicMax(&s_mw, mw); atomicMin(&s_fv, mf);
    }
    __syncthreads();
    // one coalesced 4KB store of this block's histogram
    reinterpret_cast<int4*>(g_bh + blockIdx.x * NBB)[t] =
        make_int4(sh[t * 4], sh[t * 4 + 1], sh[t * 4 + 2], sh[t * 4 + 3]);
    if (t == 0) {
        atomicMax(&g_maxah_b, s_mh);
        atomicMax(&g_maxaw_b, s_mw);
        if (s_fv != 0x7FFFFFFF) atomicMin(&g_first_valid, s_fv);
    }
}

// ----------- per-bin scan over blocks: g_bh -> exclusive offsets ------------
__global__ void __launch_bounds__(TPB) k_scanA(int nb) {
    __shared__ int ssum[TPB];
    int bin = blockIdx.x;
    int t = threadIdx.x;
    int v[4]; int loc = 0;
    #pragma unroll
    for (int i = 0; i < 4; i++) {
        int blk = t * 4 + i;
        v[i] = (blk < nb) ? g_bh[blk * NBB + bin] : 0;
        loc += v[i];
    }
    ssum[t] = loc;
    __syncthreads();
    for (int off = 1; off < TPB; off <<= 1) {
        int x = (t >= off) ? ssum[t - off] : 0;
        __syncthreads();
        ssum[t] += x;
        __syncthreads();
    }
    int run = ssum[t] - loc;
    #pragma unroll
    for (int i = 0; i < 4; i++) {
        int blk = t * 4 + i;
        if (blk < nb) g_bh[blk * NBB + bin] = run;
        run += v[i];
    }
    if (t == TPB - 1) g_ahist[bin] = run;   // bin total
}

// -------------------- scan bin totals + init column keys --------------------
__global__ void __launch_bounds__(NBB) k_scan(int A) {
    __shared__ int s[NBB];
    int t = threadIdx.x;
    int c = g_ahist[t];
    s[t] = c;
    __syncthreads();
    for (int off = 1; off < NBB; off <<= 1) {
        int v = (t >= off) ? s[t - off] : 0;
        __syncthreads();
        s[t] += v;
        __syncthreads();
    }
    g_abinstart[t] = s[t] - c;
    if (t == NBB - 1) g_abinstart[NBB] = s[t];
    if (t < MAXG) {
        int fv = g_first_valid;
        unsigned long long key;
        if (fv < A)  // (iou=0, idx=first_valid): argmax when column has no positive iou
            key = ((unsigned long long)0x80000000u << 32) | (unsigned long long)(~(unsigned)fv);
        else         // all invalid: argmax of all-(-1) = 0
            key = ((unsigned long long)0x407FFFFFu << 32) | 0xFFFFFFFFull;
        g_colkey[t] = key;
    }
}

// ------------- scatter anchors into bins (shared-atomic ranking) ------------
__global__ void __launch_bounds__(TPB) k_scat(const float4* __restrict__ anchors,
                                              const void* __restrict__ mask, int A) {
    __shared__ int s_off[NBB];
    int t = threadIdx.x;
    const int4* bh4 = reinterpret_cast<const int4*>(g_bh + blockIdx.x * NBB);
    const int4* bs4 = reinterpret_cast<const int4*>(g_abinstart);
    int4 o = bh4[t], s = bs4[t];
    s_off[t * 4]     = o.x + s.x;
    s_off[t * 4 + 1] = o.y + s.y;
    s_off[t * 4 + 2] = o.z + s.z;
    s_off[t * 4 + 3] = o.w + s.w;
    __syncthreads();
    int a = blockIdx.x * TPB + t;
    if (a >= A) return;
    float4 b = anchors[a];
    int bin = binOf(b.x) * NB + binOf(b.y);
    int p = atomicAdd(&s_off[bin], 1);
    float area = (b.z - b.x) * (b.w - b.y);
    bool valid = mask_at(mask, g_mask_kind, a);
    g_spack[2 * p]     = b;
    g_spack[2 * p + 1] = make_float4(valid ? area : -area, __int_as_float(a), 0.f, 0.f);
}

// ---------------- row pass: per-anchor max/argmax over windowed GTs ---------
__global__ void __launch_bounds__(TPB) k_row(int A, int G) {
    __shared__ float4 s_gb[MAXG];
    __shared__ float  s_ga[MAXG];
    __shared__ int    s_gm[MAXG];
    __shared__ int    s_gs[NBB + 1];
    int t = threadIdx.x;
    for (int i = t; i < G; i += TPB) {
        s_gb[i] = g_gbox[i]; s_ga[i] = g_garea[i]; s_gm[i] = g_gmeta[i];
    }
    for (int i = t; i < NBB + 1; i += TPB) s_gs[i] = g_gstart[i];
    __syncthreads();

    int p = blockIdx.x * TPB + t;
    if (p >= A) return;
    float4 ab = g_spack[2 * p];
    float4 mt = g_spack[2 * p + 1];
    float aarea = fabsf(mt.x);
    int orig = __float_as_int(mt.y);

    float maxgh = __uint_as_float(g_maxgh_b), maxgw = __uint_as_float(g_maxgw_b);
    float maxah = __uint_as_float(g_maxah_b), maxaw = __uint_as_float(g_maxaw_b);
    int aby = binOf(ab.x), abx = binOf(ab.y);
    // uniform-per-bin superset window: includes every GT that can intersect
    int by0 = binOf(fmaxf(aby * 32.f - maxgh, 0.f));
    int by1 = binOf(aby * 32.f + 32.f + maxah);
    int bx0 = binOf(fmaxf(abx * 32.f - maxgw, 0.f));
    int bx1 = binOf(abx * 32.f + 32.f + maxaw);

    float bi = 0.f, bc = 1.f;           // best (inter, area_a+area_g); iou = bi/(bc-bi)
    int bg = g_first_noncrowd;          // argmax default = first non-crowd GT
    float ci = 0.f, cc = 1.f;           // crowd best

    for (int by = by0; by <= by1; by++) {
        int s = s_gs[by * NB + bx0];
        int e = s_gs[by * NB + bx1 + 1];
        for (int i = s; i < e; i++) {
            float4 gb = s_gb[i];
            float iy1 = fmaxf(ab.x, gb.x);
            float ix1 = fmaxf(ab.y, gb.y);
            float iy2 = fminf(ab.z, gb.z);
            float ix2 = fminf(ab.w, gb.w);
            float inter = fmaxf(iy2 - iy1, 0.f) * fmaxf(ix2 - ix1, 0.f);
            float c = aarea + s_ga[i];
            int m = s_gm[i];
            if (m < 0) { if (inter * cc > ci * c) { ci = inter; cc = c; } }
            else       { if (inter * bc > bi * c) { bi = inter; bc = c; bg = m; } }
        }
    }
    float bu = bc - bi;
    int fl = 0;
    if (bi >= 0.7f * bu) fl |= 1;
    if (bi <  0.3f * bu) fl |= 2;
    if (ci < 0.001f * (cc - ci)) fl |= 4;     // no_crowd (trivially true if no crowd hits)
    g_fb[orig] = fl | (bg << 4);
}

// -------------- column pass: per-GT argmax over windowed valid anchors ------
__global__ void __launch_bounds__(TPB) k_col(const float4* __restrict__ gtb, int A) {
    __shared__ float s_bi[TPB], s_bc[TPB];
    __shared__ int s_bp[TPB];
    int g = blockIdx.x;
    int t = threadIdx.x;
    float4 gb = gtb[g];
    float garea = (gb.z - gb.x) * (gb.w - gb.y);
    float maxah = __uint_as_float(g_maxah_b), maxaw = __uint_as_float(g_maxaw_b);
    int by0 = binOf(fmaxf(gb.x - maxah, 0.f));
    int by1 = binOf(gb.z);
    int bx0 = binOf(fmaxf(gb.y - maxaw, 0.f));
    int bx1 = binOf(gb.w);

    float bi = 0.f, bc = 1.f; int bp = -1;
    for (int by = by0; by <= by1; by++) {
        int s = g_abinstart[by * NB + bx0];
        int e = g_abinstart[by * NB + bx1 + 1];
        for (int i = s + t; i < e; i += TPB) {
            float4 mt = g_spack[2 * i + 1];
            float av = mt.x;
            if (av <= 0.f) continue;         // invalid anchor
            float4 ab = g_spack[2 * i];
            float iy1 = fmaxf(ab.x, gb.x);
            float ix1 = fmaxf(ab.y, gb.y);
            float iy2 = fminf(ab.z, gb.z);
            float ix2 = fminf(ab.w, gb.w);
            float inter = fmaxf(iy2 - iy1, 0.f) * fmaxf(ix2 - ix1, 0.f);
            float c = av + garea;
            if (inter * bc > bi * c) { bi = inter; bc = c; bp = i; }
        }
    }
    s_bi[t] = bi; s_bc[t] = bc; s_bp[t] = bp;
    __syncthreads();
    for (int off = TPB / 2; off > 0; off >>= 1) {
        if (t < off) {
            float oi = s_bi[t + off], oc = s_bc[t + off];
            if (oi * s_bc[t] > s_bi[t] * oc) {
                s_bi[t] = oi; s_bc[t] = oc; s_bp[t] = s_bp[t + off];
            }
        }
        __syncthreads();
    }
    if (t == 0 && s_bp[0] >= 0) {
        int idx = __float_as_int(g_spack[2 * s_bp[0] + 1].y);
        float iou = s_bi[0] / (s_bc[0] - s_bi[0]);
        unsigned long long key =
            ((unsigned long long)mono_f2u(iou) << 32) | (unsigned long long)(~(unsigned)idx);
        atomicMax(&g_colkey[g], key);
    }
}

// --------------------- scatter pos_from_gt (non-crowd GTs) ------------------
__global__ void k_posgt(const int* __restrict__ gt_cls, int G, int A) {
    int g = blockIdx.x * blockDim.x + threadIdx.x;
    if (g < G && gt_cls[g] >= 0) {
        unsigned idx = ~(unsigned)(g_colkey[g] & 0xFFFFFFFFull);
        if (idx < (unsigned)A) atomicOr(&g_fb[idx], 8);
    }
}

// ------------------------------- finalize -----------------------------------
__global__ void __launch_bounds__(TPB) k_final(
    const float4* __restrict__ anchors, const void* __restrict__ mask,
    const float4* __restrict__ gtb, const float* __restrict__ stddev,
    float* __restrict__ out, int A)
{
    int a = blockIdx.x * TPB + threadIdx.x;
    bool pos_valid = false;
    if (a < A) {
        int v = g_fb[a];
        bool valid = mask_at(mask, g_mask_kind, a);
        bool positive = (v & 9) != 0;
        bool negative = ((v & 2) != 0) && ((v & 4) != 0) && !positive;
        int match = positive ? 1 : (negative ? -1 : 0);
        if (!valid) match = 0;
        out[a] = (float)match;

        pos_valid = positive && valid;
        float4 d = make_float4(0.f, 0.f, 0.f, 0.f);
        if (pos_valid) {
            float4 m  = gtb[v >> 4];
            float4 ab = anchors[a];
            // faithful to source bug: size = b[2:4] + b[0:2]
            float gsy = m.z + m.x,   gsx = m.w + m.y;
            float asy = ab.z + ab.x, asx = ab.w + ab.y;
            float gcy = gsy * 0.5f, gcx = gsx * 0.5f;
            float acy = asy * 0.5f, acx = asx * 0.5f;
            d.x = ((gcy - acy) / asy) / stddev[0];
            d.y = ((gcx - acx) / asx) / stddev[1];
            d.z = logf(gsy / asy) / stddev[2];
            d.w = logf(gsx / asx) / stddev[3];
        }
        reinterpret_cast<float4*>(out + A)[a] = d;
    }
    unsigned bal = __ballot_sync(0xFFFFFFFFu, pos_valid);
    if ((threadIdx.x & 31) == 0 && bal) atomicAdd(&g_num_pos, __popc(bal));
    __syncthreads();
    if (threadIdx.x == 0) {
        __threadfence();
        int tk = atomicAdd(&g_ticket, 1);
        if (tk == (int)gridDim.x - 1) {
            g_ticket = 0;
            out[5 * A] = (float)atomicAdd(&g_num_pos, 0);
        }
    }
}

// ------------------------------- launcher -----------------------------------
extern "C" void kernel_launch(void* const* d_in, const int* in_sizes, int n_in,
                              void* d_out, int out_size) {
    const float4* anchors = (const float4*)d_in[0];
    const void*   mask    = d_in[1];
    const int*    gt_cls  = (const int*)d_in[2];
    const float4* gtb     = (const float4*)d_in[3];
    const float*  stddev  = (const float*)d_in[4];
    int A = in_sizes[0] / 4;
    int G = in_sizes[2];
    float* out = (float*)d_out;
    int nb = (A + TPB - 1) / TPB;

    k_prep <<<1,   TPB>>>(mask, A, gt_cls, gtb, G);
    k_hist <<<nb,  TPB>>>(anchors, mask, A);
    k_scanA<<<NBB, TPB>>>(nb);
    k_scan <<<1,   NBB>>>(A);
    k_scat <<<nb,  TPB>>>(anchors, mask, A);
    k_row  <<<nb,  TPB>>>(A, G);
    k_col  <<<G,   TPB>>>(gtb, A);
    k_posgt<<<(G + TPB - 1) / TPB, TPB>>>(gt_cls, G, A);
    k_final<<<nb,  TPB>>>(anchors, mask, gtb, stddev, out, A);
}

// round 11
// speedup vs baseline: 1.5461x; 1.0650x over previous
#include <cuda_runtime.h>
#include <cstdint>

// ---------------------------------------------------------------------------
// RPN target assignment, 2-kernel version.
// k_main: prep(in block0) + per-anchor windowed row scan + fused column
//         argmax reduction (smem u64 keys -> global atomicMax) + posgt in
//         last-block ticket.
// k_final: outputs.
// Outputs (float32): rpn_match [A], rpn_bbox [A,4], num_pos [1]
// ---------------------------------------------------------------------------

#define MAX_A 262144
#define MAXG  512
#define TPB   256
#define NB    32
#define NBB   1024

__device__ int g_mask_kind;                  // 0=uint8, 1=int32, 2=float32
__device__ volatile int g_ready;             // zero-init; reset by last block
__device__ int g_ticket, g_ticket2;          // zero-init; self-resetting
__device__ int g_num_pos;
__device__ int g_first_valid = 0x7FFFFFFF;   // reset each launch in prep
__device__ int g_first_noncrowd;
__device__ unsigned g_maxgh_b, g_maxgw_b;    // max GT h/w (float bits)
__device__ int    g_gstart[NBB + 1];
__device__ float4 g_gbox[MAXG];
__device__ float  g_garea[MAXG];
__device__ int    g_gmeta[MAXG];             // orig g | (crowd ? 0x80000000 : 0)
__device__ unsigned long long g_colkey[MAXG];// zero-init; reset each launch
__device__ int g_fb[MAX_A];                  // bits0-3 flags, bits4+ best GT

__device__ __forceinline__ bool mask_at(const void* m, int kind, int i) {
    if (kind == 0) return ((const unsigned char*)m)[i] != 0;
    if (kind == 1) return ((const int*)m)[i] != 0;
    return ((const float*)m)[i] != 0.0f;
}

__device__ __forceinline__ int binOf(float v) {
    int b = (int)(v * 0.03125f);             // /32; callers pass v >= 0
    return b < 0 ? 0 : (b > NB - 1 ? NB - 1 : b);
}

// ------------------------------ main kernel ---------------------------------
__global__ void __launch_bounds__(TPB) k_main(
    const float4* __restrict__ anchors, const void* __restrict__ mask,
    const int* __restrict__ gt_cls, const float4* __restrict__ gtb,
    int A, int G)
{
    __shared__ float4 s_gb[MAXG];
    __shared__ float  s_ga[MAXG];
    __shared__ int    s_gm[MAXG];        // prep reuses [0..TPB) as scan buffer
    __shared__ int    s_gs[NBB + 1];     // prep reuses as GT histogram
    __shared__ unsigned long long s_col[MAXG];
    __shared__ int s_misc[8];            // 0:fnc 1:mh 2:mw 3:flag 4..7:nz

    const int t = threadIdx.x;

    if (blockIdx.x == 0) {
        // ---------------- prep (block 0 only) ----------------
        if (t < 8) s_misc[t] = (t == 0) ? 0x7FFFFFFF : 0;
        for (int i = t; i < NBB; i += TPB) s_gs[i] = 0;
        if (t == 0) { g_num_pos = 0; g_first_valid = 0x7FFFFFFF; }
        __syncthreads();
        // mask dtype detection on first min(A,1024) bytes (values are 0/1)
        {
            const unsigned char* p = (const unsigned char*)mask;
            int nbytes = A < 1024 ? A : 1024;
            for (int i = t; i < nbytes; i += TPB)
                if (p[i]) atomicAdd(&s_misc[4 + (i & 3)], 1);
        }
        for (int g = t; g < G; g += TPB) {
            float4 b = gtb[g];
            atomicAdd(&s_gs[binOf(b.x) * NB + binOf(b.y)], 1);
            atomicMax((unsigned*)&s_misc[1], __float_as_uint(b.z - b.x));
            atomicMax((unsigned*)&s_misc[2], __float_as_uint(b.w - b.y));
            if (gt_cls[g] >= 0) atomicMin(&s_misc[0], g);
        }
        __syncthreads();
        // exclusive scan of s_gs[NBB] (4 bins/thread, Hillis-Steele on sums)
        int base = t * 4;
        int c0 = s_gs[base], c1 = s_gs[base + 1], c2 = s_gs[base + 2], c3 = s_gs[base + 3];
        int local = c0 + c1 + c2 + c3;
        s_gm[t] = local;
        __syncthreads();
        for (int off = 1; off < TPB; off <<= 1) {
            int v = (t >= off) ? s_gm[t - off] : 0;
            __syncthreads();
            s_gm[t] += v;
            __syncthreads();
        }
        int excl = s_gm[t] - local;
        s_gs[base]     = excl;
        s_gs[base + 1] = excl + c0;
        s_gs[base + 2] = excl + c0 + c1;
        s_gs[base + 3] = excl + c0 + c1 + c2;
        g_gstart[base]     = s_gs[base];
        g_gstart[base + 1] = s_gs[base + 1];
        g_gstart[base + 2] = s_gs[base + 2];
        g_gstart[base + 3] = s_gs[base + 3];
        if (t == 0) g_gstart[NBB] = G;
        __syncthreads();
        // scatter GTs into bin-sorted arrays
        for (int g = t; g < G; g += TPB) {
            float4 b = gtb[g];
            bool crowd = gt_cls[g] < 0;
            int pos = atomicAdd(&s_gs[binOf(b.x) * NB + binOf(b.y)], 1);
            g_gbox[pos]  = b;
            g_garea[pos] = (b.z - b.x) * (b.w - b.y);
            g_gmeta[pos] = g | (crowd ? 0x80000000 : 0);
        }
        __syncthreads();
        if (t == 0) {
            int nz0 = s_misc[4], nz1 = s_misc[5], nz2 = s_misc[6], nz3 = s_misc[7];
            int kind;
            if (nz0 == 0 && (nz2 + nz3) > 0)            kind = 2;  // float32
            else if (nz1 == 0 && nz2 == 0 && nz3 == 0)  kind = 1;  // int32
            else                                        kind = 0;  // uint8/bool
            g_mask_kind = kind;
            g_first_noncrowd = (s_misc[0] == 0x7FFFFFFF) ? 0 : s_misc[0];
            g_maxgh_b = (unsigned)s_misc[1];
            g_maxgw_b = (unsigned)s_misc[2];
            __threadfence();
            g_ready = 1;     // release
        }
        __syncthreads();
    } else {
        if (t == 0) { while (g_ready == 0) __nanosleep(128); }
        __syncthreads();
        __threadfence();     // acquire side of the flag
    }

    // ---------------- row phase (all blocks) ----------------
    const int kind = g_mask_kind;
    for (int i = t; i < G; i += TPB) {
        s_gb[i] = g_gbox[i]; s_ga[i] = g_garea[i]; s_gm[i] = g_gmeta[i];
        s_col[i] = 0ull;
    }
    for (int i = t; i < NBB + 1; i += TPB) s_gs[i] = g_gstart[i];
    __syncthreads();

    const int a = blockIdx.x * TPB + t;
    bool valid = false;
    int myfv = 0x7FFFFFFF;
    if (a < A) {
        valid = mask_at(mask, kind, a);
        if (valid) myfv = a;
    }
    int wmin = __reduce_min_sync(0xFFFFFFFFu, myfv);
    if ((t & 31) == 0 && wmin != 0x7FFFFFFF) atomicMin(&g_first_valid, wmin);

    if (a < A && valid) {
        float4 ab = anchors[a];
        float aarea = (ab.z - ab.x) * (ab.w - ab.y);
        float maxgh = __uint_as_float(g_maxgh_b);
        float maxgw = __uint_as_float(g_maxgw_b);
        // superset window: every GT with positive intersection has
        // g.y1 in (a.y1 - maxgh, a.y2), g.x1 in (a.x1 - maxgw, a.x2)
        int by0 = binOf(fmaxf(ab.x - maxgh, 0.f)), by1 = binOf(ab.z);
        int bx0 = binOf(fmaxf(ab.y - maxgw, 0.f)), bx1 = binOf(ab.w);

        float biou = 0.f;                  // row best iou (non-crowd)
        int   bg   = g_first_noncrowd;     // row argmax default
        float cmax = 0.f;                  // crowd max iou
        unsigned akey = ~(unsigned)a;

        for (int by = by0; by <= by1; by++) {
            int s = s_gs[by * NB + bx0];
            int e = s_gs[by * NB + bx1 + 1];
            for (int i = s; i < e; i++) {
                float4 gb = s_gb[i];
                float iy1 = fmaxf(ab.x, gb.x);
                float ix1 = fmaxf(ab.y, gb.y);
                float iy2 = fminf(ab.z, gb.z);
                float ix2 = fminf(ab.w, gb.w);
                float inter = fmaxf(iy2 - iy1, 0.f) * fmaxf(ix2 - ix1, 0.f);
                if (inter > 0.f) {
                    float iou = inter / ((aarea + s_ga[i]) - inter);   // same expr as ref
                    int m = s_gm[i];
                    if (m < 0) {
                        cmax = fmaxf(cmax, iou);
                    } else {
                        if (iou > biou) { biou = iou; bg = m; }
                        unsigned long long key =
                            ((unsigned long long)(__float_as_uint(iou) | 0x80000000u) << 32)
                            | (unsigned long long)akey;
                        atomicMax(&s_col[i], key);
                    }
                }
            }
        }
        int fl = 0;
        if (biou >= 0.7f) fl |= 1;
        if (biou <  0.3f) fl |= 2;
        if (cmax <  0.001f) fl |= 4;       // no_crowd
        g_fb[a] = fl | (bg << 4);
    }
    __syncthreads();

    // flush per-GT column keys to global (orig-g indexed)
    for (int i = t; i < G; i += TPB) {
        unsigned long long k = s_col[i];
        if (k) atomicMax(&g_colkey[s_gm[i] & 0x7FFFFFFF], k);
    }
    __syncthreads();

    // last-block ticket: pos_from_gt scatter + state reset
    if (t == 0) {
        __threadfence();
        int tk = atomicAdd(&g_ticket, 1);
        s_misc[3] = (tk == (int)gridDim.x - 1);
        if (s_misc[3]) g_ticket = 0;
    }
    __syncthreads();
    if (s_misc[3]) {
        int fv = g_first_valid;
        for (int g = t; g < G; g += TPB) {
            unsigned long long k = g_colkey[g];
            unsigned idx = k ? ~(unsigned)(k & 0xFFFFFFFFull)
                             : (unsigned)((fv < A) ? fv : 0);
            if (gt_cls[g] >= 0) atomicOr(&g_fb[idx], 8);
            g_colkey[g] = 0ull;            // reset for next launch
        }
        if (t == 0) { __threadfence(); g_ready = 0; }
    }
}

// ------------------------------- finalize -----------------------------------
__global__ void __launch_bounds__(TPB) k_final(
    const float4* __restrict__ anchors, const void* __restrict__ mask,
    const float4* __restrict__ gtb, const float* __restrict__ stddev,
    float* __restrict__ out, int A)
{
    int a = blockIdx.x * TPB + threadIdx.x;
    bool pos_valid = false;
    if (a < A) {
        int v = g_fb[a];
        bool valid = mask_at(mask, g_mask_kind, a);
        bool positive = (v & 9) != 0;                       // iou>=0.7 | pos_from_gt
        bool negative = ((v & 2) != 0) && ((v & 4) != 0) && !positive;
        int match = positive ? 1 : (negative ? -1 : 0);
        if (!valid) match = 0;
        out[a] = (float)match;

        pos_valid = positive && valid;
        float4 d = make_float4(0.f, 0.f, 0.f, 0.f);
        if (pos_valid) {
            float4 m  = gtb[v >> 4];
            float4 ab = anchors[a];
            // faithful to source bug: size = b[2:4] + b[0:2]
            float gsy = m.z + m.x,   gsx = m.w + m.y;
            float asy = ab.z + ab.x, asx = ab.w + ab.y;
            float gcy = gsy * 0.5f, gcx = gsx * 0.5f;
            float acy = asy * 0.5f, acx = asx * 0.5f;
            d.x = ((gcy - acy) / asy) / stddev[0];
            d.y = ((gcx - acx) / asx) / stddev[1];
            d.z = logf(gsy / asy) / stddev[2];
            d.w = logf(gsx / asx) / stddev[3];
        }
        reinterpret_cast<float4*>(out + A)[a] = d;
    }
    unsigned bal = __ballot_sync(0xFFFFFFFFu, pos_valid);
    if ((threadIdx.x & 31) == 0 && bal) atomicAdd(&g_num_pos, __popc(bal));
    __syncthreads();
    if (threadIdx.x == 0) {
        __threadfence();
        int tk = atomicAdd(&g_ticket2, 1);
        if (tk == (int)gridDim.x - 1) {
            g_ticket2 = 0;
            out[5 * A] = (float)atomicAdd(&g_num_pos, 0);
        }
    }
}

// ------------------------------- launcher -----------------------------------
extern "C" void kernel_launch(void* const* d_in, const int* in_sizes, int n_in,
                              void* d_out, int out_size) {
    const float4* anchors = (const float4*)d_in[0];
    const void*   mask    = d_in[1];
    const int*    gt_cls  = (const int*)d_in[2];
    const float4* gtb     = (const float4*)d_in[3];
    const float*  stddev  = (const float*)d_in[4];
    int A = in_sizes[0] / 4;
    int G = in_sizes[2];
    float* out = (float*)d_out;
    int nb = (A + TPB - 1) / TPB;

    k_main <<<nb, TPB>>>(anchors, mask, gt_cls, gtb, A, G);
    k_final<<<nb, TPB>>>(anchors, mask, gtb, stddev, out, A);
}